// round 7
// baseline (speedup 1.0000x reference)
#include <cuda_runtime.h>
#include <cuda_bf16.h>

#define HW      65536
#define WMASK   255
#define NROWS   600
#define NPAD    640
#define TT      60
#define NT      64
#define CLS     91
#define KSLICES 32
#define KSPAN   2048
#define KSTEPS  (KSPAN/16)   // 128
#define MTILES  10
#define TCHUNKS 16
#define TCHUNK  (HW/TCHUNKS) // 4096

#define PREP_BFRAG 4096
#define PREP_TSTAT (TT*TCHUNKS)   // 960
#define PREP_ZERO  10
#define PREP_GRID  (PREP_BFRAG + PREP_TSTAT + PREP_ZERO)

// ---------------- scratch (static, no allocation) ----------------
__device__ float g_partP[KSLICES*NPAD*NT];   // per-kslice partial p.t^T
__device__ float g_partD[KSLICES*NPAD*NT];   // per-kslice partial (pos-neg).t^T
__device__ float g_partNS[KSLICES*NPAD];     // per-kslice partial sum(neg)
__device__ unsigned g_pmm[NPAD*4];           // pred mask box min/max (monotone-uint)
__device__ __align__(16) unsigned g_bfrag[4096*32*16];  // B in mma fragment order, 8MB
// target stats chunk partials (unique writer -> deterministic, no atomics)
__device__ float g_tc [TCHUNKS*NT];
__device__ float g_txn[TCHUNKS*NT];
__device__ float g_tyn[TCHUNKS*NT];
__device__ float g_txx[TCHUNKS*NT];
__device__ float g_tyx[TCHUNKS*NT];

// monotone float<->orderable-uint
__device__ __forceinline__ unsigned f2o(float f){
  unsigned u = __float_as_uint(f);
  return (u & 0x80000000u) ? ~u : (u | 0x80000000u);
}
__device__ __forceinline__ float o2f(unsigned u){
  return __uint_as_float((u & 0x80000000u) ? (u & 0x7FFFFFFFu) : ~u);
}

__device__ __forceinline__ unsigned pack2(float a, float b){
  __nv_bfloat162 h = __floats2bfloat162_rn(a, b);
  return *reinterpret_cast<unsigned*>(&h);
}

__device__ __forceinline__ void mma16816(float* c, unsigned a0,unsigned a1,unsigned a2,unsigned a3,
                                         unsigned b0, unsigned b1){
  asm volatile("mma.sync.aligned.m16n8k16.row.col.f32.bf16.bf16.f32 "
    "{%0,%1,%2,%3}, {%4,%5,%6,%7}, {%8,%9}, {%0,%1,%2,%3};\n"
    : "+f"(c[0]), "+f"(c[1]), "+f"(c[2]), "+f"(c[3])
    : "r"(a0), "r"(a1), "r"(a2), "r"(a3), "r"(b0), "r"(b1));
}

// ---------------- fused prep: bfrag + tstats partials + pmm init ----------------
__global__ void k_prep(const int* __restrict__ tm){
  const int bid = blockIdx.x;
  const int tid = threadIdx.x;

  if (bid < PREP_BFRAG){
    // ---- B fragment build (targets, bf16, mma layout) ----
    __shared__ unsigned short Bt[64][16];  // [n][k] bf16 bits
    const int s = bid;                     // global k-step (0..4095)
    for (int e = tid; e < 64*16; e += 256){
      int ki = e & 15, n = e >> 4;
      float v;
      if (n < TT)       v = (float)tm[n*HW + s*16 + ki];
      else if (n == TT) v = 1.0f;          // ones column -> row sums of p
      else              v = 0.0f;
      Bt[n][ki] = __bfloat16_as_ushort(__float2bfloat16(v));
    }
    __syncthreads();
    const int l = tid >> 3, t = tid & 7;
    const int tig = l & 3, g = l >> 2;
    const int n = t*8 + g;
    unsigned r0 = *(const unsigned*)&Bt[n][tig*2];
    unsigned r1 = *(const unsigned*)&Bt[n][tig*2 + 8];
    unsigned base = (unsigned)(s*32 + l)*16 + t*2;
    g_bfrag[base]   = r0;
    g_bfrag[base+1] = r1;
    return;
  }

  if (bid < PREP_BFRAG + PREP_TSTAT){
    // ---- target stats chunk partials ----
    const int b2 = bid - PREP_BFRAG;
    const int j = b2 % TT;
    const int chunk = b2 / TT;
    const int base = chunk * TCHUNK;
    float cnt = 0.f, xmn = 1e8f, ymn = 1e8f, xmx = 0.f, ymx = 0.f;
    for (int o = tid; o < TCHUNK; o += 256){
      int px = base + o;
      int m = tm[j*HW + px];
      if (m){
        float xc = (float)(px & WMASK), yc = (float)(px >> 8);
        cnt += 1.f;
        xmn = fminf(xmn, xc); ymn = fminf(ymn, yc);
        xmx = fmaxf(xmx, xc); ymx = fmaxf(ymx, yc);
      }
    }
    for (int o=16;o>0;o>>=1){
      cnt += __shfl_down_sync(0xffffffffu, cnt, o);
      xmn = fminf(xmn, __shfl_down_sync(0xffffffffu, xmn, o));
      ymn = fminf(ymn, __shfl_down_sync(0xffffffffu, ymn, o));
      xmx = fmaxf(xmx, __shfl_down_sync(0xffffffffu, xmx, o));
      ymx = fmaxf(ymx, __shfl_down_sync(0xffffffffu, ymx, o));
    }
    __shared__ float sc[8], sxn[8], syn[8], sxx[8], syx[8];
    int w = tid >> 5;
    if ((tid & 31) == 0){ sc[w]=cnt; sxn[w]=xmn; syn[w]=ymn; sxx[w]=xmx; syx[w]=ymx; }
    __syncthreads();
    if (tid == 0){
      float c=0.f, a=1e8f, b=1e8f, cx=0.f, cy=0.f;
      for (int k=0;k<8;k++){
        c += sc[k];
        a = fminf(a, sxn[k]); b = fminf(b, syn[k]);
        cx = fmaxf(cx, sxx[k]); cy = fmaxf(cy, syx[k]);
      }
      g_tc [chunk*NT + j] = c;
      g_txn[chunk*NT + j] = a;
      g_tyn[chunk*NT + j] = b;
      g_txx[chunk*NT + j] = cx;
      g_tyx[chunk*NT + j] = cy;
    }
    return;
  }

  // ---- init pred-mask min/max state ----
  {
    int i = (bid - PREP_BFRAG - PREP_TSTAT)*256 + tid;
    if (i < NPAD*4) g_pmm[i] = ((i&3) < 2) ? 0xFFFFFFFFu : 0u;
  }
}

// ---------------- main: sigmoid/focal transform + tensor-core dots + fused box min/max ----------------
// per float2: p = sigmoid(x); -log p = log1p(e^-x); -log(1-p) = x + log1p(e^-x)
#define TF2(xv, XC, YC, pr, dr, nsacc, XMX, XMN, YMX, YMN) {                    \
  float x0_ = (xv).x, x1_ = (xv).y;                                             \
  float e0_ = __expf(-x0_), e1_ = __expf(-x1_);                                 \
  float P0_ = __fdividef(1.f, 1.f+e0_), P1_ = __fdividef(1.f, 1.f+e1_);         \
  float S0_ = __logf(1.f+e0_), S1_ = __logf(1.f+e1_);                           \
  float n0_ = 0.75f*P0_*P0_*(x0_+S0_), n1_ = 0.75f*P1_*P1_*(x1_+S1_);           \
  float o0_ = 1.f-P0_, o1_ = 1.f-P1_;                                           \
  float D0_ = 0.25f*o0_*o0_*S0_ - n0_, D1_ = 0.25f*o1_*o1_*S1_ - n1_;           \
  nsacc += n0_ + n1_;                                                           \
  { float xc0_ = (XC), xc1_ = (XC) + 1.f, yc_ = (YC);                           \
    float a_ = x0_*xc0_, b_ = x0_*yc_, c_ = x1_*xc1_, d2_ = x1_*yc_;            \
    XMX = fmaxf(XMX, fmaxf(a_, c_));                                            \
    YMX = fmaxf(YMX, fmaxf(b_, d2_));                                           \
    XMN = fminf(XMN, fminf(x0_!=0.f?a_:1e8f,  x1_!=0.f?c_:1e8f));               \
    YMN = fminf(YMN, fminf(x0_!=0.f?b_:1e8f,  x1_!=0.f?d2_:1e8f)); }            \
  pr = pack2(P0_, P1_); dr = pack2(D0_, D1_); }

#define QSUM(v) { v += __shfl_down_sync(0xffffffffu, v, 2); v += __shfl_down_sync(0xffffffffu, v, 1); }
#define QMAX(v) { v = fmaxf(v, __shfl_down_sync(0xffffffffu, v, 2)); v = fmaxf(v, __shfl_down_sync(0xffffffffu, v, 1)); }
#define QMIN(v) { v = fminf(v, __shfl_down_sync(0xffffffffu, v, 2)); v = fminf(v, __shfl_down_sync(0xffffffffu, v, 1)); }

// load one k-step (16 cols) for both rows: 4 independent LDG.64
#define LOADA(buf, sidx) {                                                      \
  int c_ = kbase + (sidx)*16 + tig*2;                                           \
  float2 z_ = make_float2(0.f, 0.f);                                            \
  buf[0] = vlo ? *(const float2*)(Alo + c_)     : z_;                           \
  buf[1] = vhi ? *(const float2*)(Ahi + c_)     : z_;                           \
  buf[2] = vlo ? *(const float2*)(Alo + c_ + 8) : z_;                           \
  buf[3] = vhi ? *(const float2*)(Ahi + c_ + 8) : z_; }

// process one k-step: B frag load + 4 TF2 + 16 MMA + coord advance
#define PROC(buf, sidx) {                                                       \
  const uint4* bp_ = (const uint4*)(bbase + (size_t)(sidx)*512);                \
  uint4 q0 = bp_[0], q1 = bp_[1], q2 = bp_[2], q3 = bp_[3];                     \
  unsigned ap0,ad0,ap1,ad1,ap2,ad2,ap3,ad3;                                     \
  float xcl_ = fxb + ltig2;                                                     \
  TF2(buf[0], xcl_,     fy, ap0, ad0, ns_lo, xmx_lo, xmn_lo, ymx_lo, ymn_lo);   \
  TF2(buf[1], xcl_,     fy, ap1, ad1, ns_hi, xmx_hi, xmn_hi, ymx_hi, ymn_hi);   \
  TF2(buf[2], xcl_+8.f, fy, ap2, ad2, ns_lo, xmx_lo, xmn_lo, ymx_lo, ymn_lo);   \
  TF2(buf[3], xcl_+8.f, fy, ap3, ad3, ns_hi, xmx_hi, xmn_hi, ymx_hi, ymn_hi);   \
  mma16816(aP+0,  ap0,ap1,ap2,ap3, q0.x,q0.y);                                  \
  mma16816(aP+4,  ap0,ap1,ap2,ap3, q0.z,q0.w);                                  \
  mma16816(aP+8,  ap0,ap1,ap2,ap3, q1.x,q1.y);                                  \
  mma16816(aP+12, ap0,ap1,ap2,ap3, q1.z,q1.w);                                  \
  mma16816(aP+16, ap0,ap1,ap2,ap3, q2.x,q2.y);                                  \
  mma16816(aP+20, ap0,ap1,ap2,ap3, q2.z,q2.w);                                  \
  mma16816(aP+24, ap0,ap1,ap2,ap3, q3.x,q3.y);                                  \
  mma16816(aP+28, ap0,ap1,ap2,ap3, q3.z,q3.w);                                  \
  mma16816(aD+0,  ad0,ad1,ad2,ad3, q0.x,q0.y);                                  \
  mma16816(aD+4,  ad0,ad1,ad2,ad3, q0.z,q0.w);                                  \
  mma16816(aD+8,  ad0,ad1,ad2,ad3, q1.x,q1.y);                                  \
  mma16816(aD+12, ad0,ad1,ad2,ad3, q1.z,q1.w);                                  \
  mma16816(aD+16, ad0,ad1,ad2,ad3, q2.x,q2.y);                                  \
  mma16816(aD+20, ad0,ad1,ad2,ad3, q2.z,q2.w);                                  \
  mma16816(aD+24, ad0,ad1,ad2,ad3, q3.x,q3.y);                                  \
  mma16816(aD+28, ad0,ad1,ad2,ad3, q3.z,q3.w);                                  \
  fxb += 16.f;                                                                  \
  if (fxb > 255.f){ fxb = 0.f; fy += 1.f; } }

__global__ void __launch_bounds__(128) k_main(const float* __restrict__ pm){
  const int kslice = blockIdx.x;     // 0..31
  const int mtile  = blockIdx.y;     // 0..9
  const int warp = threadIdx.x >> 5;
  const int lane = threadIdx.x & 31;
  const int tig  = lane & 3;
  const int g    = lane >> 2;
  const int row_lo = mtile*64 + warp*16 + g;
  const int row_hi = row_lo + 8;
  const bool vlo = row_lo < NROWS;
  const bool vhi = row_hi < NROWS;
  const float* Alo = pm + (size_t)row_lo * HW;
  const float* Ahi = pm + (size_t)row_hi * HW;
  const int kbase = kslice*KSPAN;
  const float ltig2 = (float)(tig*2);

  float aP[32], aD[32];
#pragma unroll
  for (int i=0;i<32;i++){ aP[i]=0.f; aD[i]=0.f; }
  float ns_lo=0.f, ns_hi=0.f;
  float xmx_lo=-3e38f, ymx_lo=-3e38f, xmn_lo=3e38f, ymn_lo=3e38f;
  float xmx_hi=-3e38f, ymx_hi=-3e38f, xmn_hi=3e38f, ymn_hi=3e38f;
  float fxb = 0.f;                           // (kbase & 255) == 0 since KSPAN%256==0
  float fy  = (float)(kbase >> 8);

  const unsigned* bbase = g_bfrag + (size_t)((kslice*KSTEPS)*32 + lane)*16;

  // depth-4 software pipeline: each load issued 3 PROCs (~600 cyc) before use
  float2 b0[4], b1[4], b2[4], b3[4];
  LOADA(b0, 0); LOADA(b1, 1); LOADA(b2, 2); LOADA(b3, 3);

#pragma unroll 1
  for (int s = 0; s < KSTEPS; s += 4){
    PROC(b0, s);   if (s+4 < KSTEPS) LOADA(b0, s+4);
    PROC(b1, s+1); if (s+5 < KSTEPS) LOADA(b1, s+5);
    PROC(b2, s+2); if (s+6 < KSTEPS) LOADA(b2, s+6);
    PROC(b3, s+3); if (s+7 < KSTEPS) LOADA(b3, s+7);
  }

  // write per-slice partials (unique writer per element -> deterministic)
  float* PP = g_partP + (size_t)kslice*NPAD*NT;
  float* PD = g_partD + (size_t)kslice*NPAD*NT;
#pragma unroll
  for (int t=0;t<8;t++){
    int cb = t*8 + tig*2;
    PP[row_lo*NT + cb]   = aP[t*4+0];
    PP[row_lo*NT + cb+1] = aP[t*4+1];
    PP[row_hi*NT + cb]   = aP[t*4+2];
    PP[row_hi*NT + cb+1] = aP[t*4+3];
    PD[row_lo*NT + cb]   = aD[t*4+0];
    PD[row_lo*NT + cb+1] = aD[t*4+1];
    PD[row_hi*NT + cb]   = aD[t*4+2];
    PD[row_hi*NT + cb+1] = aD[t*4+3];
  }

  QSUM(ns_lo); QSUM(ns_hi);
  QMAX(xmx_lo); QMAX(ymx_lo); QMIN(xmn_lo); QMIN(ymn_lo);
  QMAX(xmx_hi); QMAX(ymx_hi); QMIN(xmn_hi); QMIN(ymn_hi);
  if (tig == 0){
    g_partNS[kslice*NPAD + row_lo] = ns_lo;
    g_partNS[kslice*NPAD + row_hi] = ns_hi;
    atomicMin(&g_pmm[row_lo*4+0], f2o(xmn_lo));
    atomicMin(&g_pmm[row_lo*4+1], f2o(ymn_lo));
    atomicMax(&g_pmm[row_lo*4+2], f2o(xmx_lo));
    atomicMax(&g_pmm[row_lo*4+3], f2o(ymx_lo));
    atomicMin(&g_pmm[row_hi*4+0], f2o(xmn_hi));
    atomicMin(&g_pmm[row_hi*4+1], f2o(ymn_hi));
    atomicMax(&g_pmm[row_hi*4+2], f2o(xmx_hi));
    atomicMax(&g_pmm[row_hi*4+3], f2o(ymx_hi));
  }
}

// ---------------- final: per-row slice reduction + cost assembly ----------------
__device__ __forceinline__ float giou_fn(float a0,float a1,float a2,float a3,
                                         float b0,float b1,float b2,float b3){
  float area1 = (a2-a0)*(a3-a1);
  float area2 = (b2-b0)*(b3-b1);
  float ltx = fmaxf(a0,b0), lty = fmaxf(a1,b1);
  float rbx = fminf(a2,b2), rby = fminf(a3,b3);
  float wx = fmaxf(rbx-ltx, 0.f), wy = fmaxf(rby-lty, 0.f);
  float inter = wx*wy;
  float uni = area1 + area2 - inter;
  float iou = inter / uni;
  float lex = fminf(a0,b0), ley = fminf(a1,b1);
  float rex = fmaxf(a2,b2), rey = fmaxf(a3,b3);
  float ewx = fmaxf(rex-lex, 0.f), ewy = fmaxf(rey-ley, 0.f);
  float ea = ewx*ewy;
  return iou - (ea - uni)/ea;
}

__global__ void k_final(const float* __restrict__ logits, const float* __restrict__ pboxes,
                        const float* __restrict__ tboxes, const int* __restrict__ tids,
                        float* __restrict__ out){
  const int i = blockIdx.x;
  const int j = threadIdx.x;
  __shared__ float sP[NT], sD[NT], sNS;

  // deterministic slice reduction: thread j owns column j of row i
  {
    float sp = 0.f, sd = 0.f;
#pragma unroll 1
    for (int s=0;s<KSLICES;s++){
      sp += g_partP[(size_t)s*NPAD*NT + i*NT + j];
      sd += g_partD[(size_t)s*NPAD*NT + i*NT + j];
    }
    sP[j] = sp; sD[j] = sd;
  }
  if (j == 61){
    float ns = 0.f;
#pragma unroll 1
    for (int s=0;s<KSLICES;s++) ns += g_partNS[s*NPAD + i];
    sNS = ns;
  }
  __syncthreads();
  if (j >= TT) return;

  // target stats from chunk partials (deterministic)
  float tsum = 0.f, txn = 1e8f, tyn = 1e8f, txx = 0.f, tyx = 0.f;
#pragma unroll 1
  for (int c=0;c<TCHUNKS;c++){
    tsum += g_tc[c*NT + j];
    txn = fminf(txn, g_txn[c*NT + j]); tyn = fminf(tyn, g_tyn[c*NT + j]);
    txx = fmaxf(txx, g_txx[c*NT + j]); tyx = fmaxf(tyx, g_tyx[c*NT + j]);
  }

  float pcx = pboxes[i*4+0], pcy = pboxes[i*4+1], pw = pboxes[i*4+2], ph = pboxes[i*4+3];
  float p0 = pcx-0.5f*pw, p1 = pcy-0.5f*ph, p2 = pcx+0.5f*pw, p3 = pcy+0.5f*ph;

  // mask-derived pred box (xyxy) then cxcywh->xyxy (faithful to reference)
  float mx = o2f(g_pmm[i*4+0]), my = o2f(g_pmm[i*4+1]);
  float mw = o2f(g_pmm[i*4+2]), mh = o2f(g_pmm[i*4+3]);
  float q0 = mx-0.5f*mw, q1 = my-0.5f*mh, q2 = mx+0.5f*mw, q3 = my+0.5f*mh;

  float psum = sP[TT];   // ones-column -> sum(p) per row
  float nsum = sNS;

  float tcx = tboxes[j*4+0], tcy = tboxes[j*4+1], tw = tboxes[j*4+2], th = tboxes[j*4+3];
  float t0 = tcx-0.5f*tw, t1 = tcy-0.5f*th, t2 = tcx+0.5f*tw, t3 = tcy+0.5f*th;

  float cost_bbox = fabsf(pcx-tcx)+fabsf(pcy-tcy)+fabsf(pw-tw)+fabsf(ph-th);
  float g1 = giou_fn(p0,p1,p2,p3, t0,t1,t2,t3);

  float u0 = txn-0.5f*txx, u1 = tyn-0.5f*tyx, u2 = txn+0.5f*txx, u3 = tyn+0.5f*tyx;
  float g2 = giou_fn(q0,q1,q2,q3, u0,u1,u2,u3);

  int id = tids[j];
  float lg = logits[i*CLS + id];
  float pp = 1.f/(1.f + expf(-lg));
  float posc = 0.25f*(1.f-pp)*(1.f-pp)*(-logf(pp + 1e-8f));
  float negc = 0.75f*pp*pp*(-logf(1.f-pp + 1e-8f));
  float cclass = posc - negc;

  float inter = sP[j];
  float dice  = 1.f - (2.f*inter + 1e-5f)/(psum + tsum + 1e-5f);
  float dd    = sD[j];
  float focal = (dd + nsum) * (1.0f/65536.0f);

  out[i*TT + j] = cost_bbox + cclass - g1 - g2 + dice + focal;
}

// ---------------- launch ----------------
extern "C" void kernel_launch(void* const* d_in, const int* in_sizes, int n_in,
                              void* d_out, int out_size){
  (void)in_sizes; (void)n_in; (void)out_size;
  const float* logits = (const float*)d_in[0];
  const float* pboxes = (const float*)d_in[1];
  const float* pmasks = (const float*)d_in[2];
  const float* tboxes = (const float*)d_in[3];
  const int*   tids   = (const int*)d_in[4];
  const int*   tmasks = (const int*)d_in[5];
  float* out = (float*)d_out;

  k_prep<<<PREP_GRID, 256>>>(tmasks);
  k_main<<<dim3(KSLICES, MTILES), 128>>>(pmasks);
  k_final<<<NROWS, NT>>>(logits, pboxes, tboxes, tids, out);
}

// round 11
// speedup vs baseline: 1.3119x; 1.3119x over previous
#include <cuda_runtime.h>
#include <cuda_bf16.h>

#define HW      65536
#define WMASK   255
#define NROWS   600
#define NPAD    640
#define TT      60
#define NT      64
#define CLS     91
#define KSLICES 64
#define KSPAN   1024
#define KSTEPS  (KSPAN/16)   // 64
#define MTILES  10
#define DEPTH   4
#define TCHUNKS 16
#define TCHUNK  (HW/TCHUNKS) // 4096

#define PREP_BFRAG 4096
#define PREP_TSTAT (TT*TCHUNKS)   // 960
#define PREP_ZERO  10
#define PREP_GRID  (PREP_BFRAG + PREP_TSTAT + PREP_ZERO)

// ---------------- scratch (static, no allocation) ----------------
__device__ float g_partP[KSLICES*NPAD*NT];
__device__ float g_partD[KSLICES*NPAD*NT];
__device__ float g_partNS[KSLICES*NPAD];
__device__ unsigned g_pmm[NPAD*4];
__device__ __align__(16) unsigned g_bfrag[4096*32*16];  // 8MB
__device__ float g_tc [TCHUNKS*NT];
__device__ float g_txn[TCHUNKS*NT];
__device__ float g_tyn[TCHUNKS*NT];
__device__ float g_txx[TCHUNKS*NT];
__device__ float g_tyx[TCHUNKS*NT];

__device__ __forceinline__ unsigned f2o(float f){
  unsigned u = __float_as_uint(f);
  return (u & 0x80000000u) ? ~u : (u | 0x80000000u);
}
__device__ __forceinline__ float o2f(unsigned u){
  return __uint_as_float((u & 0x80000000u) ? (u & 0x7FFFFFFFu) : ~u);
}
__device__ __forceinline__ unsigned pack2(float a, float b){
  __nv_bfloat162 h = __floats2bfloat162_rn(a, b);
  return *reinterpret_cast<unsigned*>(&h);
}
__device__ __forceinline__ void mma16816(float* c, unsigned a0,unsigned a1,unsigned a2,unsigned a3,
                                         unsigned b0, unsigned b1){
  asm volatile("mma.sync.aligned.m16n8k16.row.col.f32.bf16.bf16.f32 "
    "{%0,%1,%2,%3}, {%4,%5,%6,%7}, {%8,%9}, {%0,%1,%2,%3};\n"
    : "+f"(c[0]), "+f"(c[1]), "+f"(c[2]), "+f"(c[3])
    : "r"(a0), "r"(a1), "r"(a2), "r"(a3), "r"(b0), "r"(b1));
}
__device__ __forceinline__ void cpa8(unsigned dst, const void* src){
  asm volatile("cp.async.ca.shared.global [%0], [%1], 8;\n" :: "r"(dst), "l"(src));
}
#define CP_COMMIT() asm volatile("cp.async.commit_group;\n":::"memory")
#define CP_WAIT3()  asm volatile("cp.async.wait_group 3;\n":::"memory")

// ---------------- fused prep: bfrag + tstats partials + pmm init ----------------
__global__ void k_prep(const int* __restrict__ tm){
  const int bid = blockIdx.x;
  const int tid = threadIdx.x;

  if (bid < PREP_BFRAG){
    __shared__ unsigned short Bt[64][16];
    const int s = bid;
    for (int e = tid; e < 64*16; e += 256){
      int ki = e & 15, n = e >> 4;
      float v;
      if (n < TT)       v = (float)tm[n*HW + s*16 + ki];
      else if (n == TT) v = 1.0f;
      else              v = 0.0f;
      Bt[n][ki] = __bfloat16_as_ushort(__float2bfloat16(v));
    }
    __syncthreads();
    const int l = tid >> 3, t = tid & 7;
    const int tig = l & 3, g = l >> 2;
    const int n = t*8 + g;
    unsigned r0 = *(const unsigned*)&Bt[n][tig*2];
    unsigned r1 = *(const unsigned*)&Bt[n][tig*2 + 8];
    unsigned base = (unsigned)(s*32 + l)*16 + t*2;
    g_bfrag[base]   = r0;
    g_bfrag[base+1] = r1;
    return;
  }

  if (bid < PREP_BFRAG + PREP_TSTAT){
    const int b2 = bid - PREP_BFRAG;
    const int j = b2 % TT;
    const int chunk = b2 / TT;
    const int base = chunk * TCHUNK;
    float cnt = 0.f, xmn = 1e8f, ymn = 1e8f, xmx = 0.f, ymx = 0.f;
    for (int o = tid; o < TCHUNK; o += 256){
      int px = base + o;
      int m = tm[j*HW + px];
      if (m){
        float xc = (float)(px & WMASK), yc = (float)(px >> 8);
        cnt += 1.f;
        xmn = fminf(xmn, xc); ymn = fminf(ymn, yc);
        xmx = fmaxf(xmx, xc); ymx = fmaxf(ymx, yc);
      }
    }
    for (int o=16;o>0;o>>=1){
      cnt += __shfl_down_sync(0xffffffffu, cnt, o);
      xmn = fminf(xmn, __shfl_down_sync(0xffffffffu, xmn, o));
      ymn = fminf(ymn, __shfl_down_sync(0xffffffffu, ymn, o));
      xmx = fmaxf(xmx, __shfl_down_sync(0xffffffffu, xmx, o));
      ymx = fmaxf(ymx, __shfl_down_sync(0xffffffffu, ymx, o));
    }
    __shared__ float sc[8], sxn[8], syn[8], sxx[8], syx[8];
    int w = tid >> 5;
    if ((tid & 31) == 0){ sc[w]=cnt; sxn[w]=xmn; syn[w]=ymn; sxx[w]=xmx; syx[w]=ymx; }
    __syncthreads();
    if (tid == 0){
      float c=0.f, a=1e8f, b=1e8f, cx=0.f, cy=0.f;
      for (int k=0;k<8;k++){
        c += sc[k];
        a = fminf(a, sxn[k]); b = fminf(b, syn[k]);
        cx = fmaxf(cx, sxx[k]); cy = fmaxf(cy, syx[k]);
      }
      g_tc [chunk*NT + j] = c;
      g_txn[chunk*NT + j] = a;
      g_tyn[chunk*NT + j] = b;
      g_txx[chunk*NT + j] = cx;
      g_tyx[chunk*NT + j] = cy;
    }
    return;
  }

  {
    int i = (bid - PREP_BFRAG - PREP_TSTAT)*256 + tid;
    if (i < NPAD*4) g_pmm[i] = ((i&3) < 2) ? 0xFFFFFFFFu : 0u;
  }
}

// ---------------- main ----------------
// sigmoid via tanh.approx (1 MUFU); -log p = -log P (1 MUFU); -log(1-p) = x - log P
#define TF2(xv, XC, YC, pr, dr, nsacc, XMX, XMN, YMX, YMN) {                    \
  float x0_ = (xv).x, x1_ = (xv).y;                                             \
  float t0_, t1_;                                                               \
  asm("tanh.approx.f32 %0, %1;" : "=f"(t0_) : "f"(0.5f*x0_));                   \
  asm("tanh.approx.f32 %0, %1;" : "=f"(t1_) : "f"(0.5f*x1_));                   \
  float P0_ = fmaf(0.5f, t0_, 0.5f), P1_ = fmaf(0.5f, t1_, 0.5f);               \
  float S0_ = -__logf(P0_), S1_ = -__logf(P1_);                                 \
  float n0_ = 0.75f*P0_*P0_*(x0_+S0_), n1_ = 0.75f*P1_*P1_*(x1_+S1_);           \
  float o0_ = 1.f-P0_, o1_ = 1.f-P1_;                                           \
  float D0_ = 0.25f*o0_*o0_*S0_ - n0_, D1_ = 0.25f*o1_*o1_*S1_ - n1_;           \
  nsacc += n0_ + n1_;                                                           \
  { float xc0_ = (XC), xc1_ = (XC) + 1.f, yc_ = (YC);                           \
    float a_ = x0_*xc0_, b_ = x0_*yc_, c_ = x1_*xc1_, d2_ = x1_*yc_;            \
    XMX = fmaxf(XMX, fmaxf(a_, c_));                                            \
    YMX = fmaxf(YMX, fmaxf(b_, d2_));                                           \
    XMN = fminf(XMN, fminf(x0_!=0.f?a_:1e8f,  x1_!=0.f?c_:1e8f));               \
    YMN = fminf(YMN, fminf(x0_!=0.f?b_:1e8f,  x1_!=0.f?d2_:1e8f)); }            \
  pr = pack2(P0_, P1_); dr = pack2(D0_, D1_); }

#define QSUM(v) { v += __shfl_down_sync(0xffffffffu, v, 2); v += __shfl_down_sync(0xffffffffu, v, 1); }
#define QMAX(v) { v = fmaxf(v, __shfl_down_sync(0xffffffffu, v, 2)); v = fmaxf(v, __shfl_down_sync(0xffffffffu, v, 1)); }
#define QMIN(v) { v = fminf(v, __shfl_down_sync(0xffffffffu, v, 2)); v = fminf(v, __shfl_down_sync(0xffffffffu, v, 1)); }

// issue cp.async for step s into smem buffer (s & 3); always commits a group
#define LOADA(sidx) {                                                           \
  int d_ = (sidx) & (DEPTH-1);                                                  \
  if ((sidx) < KSTEPS){                                                         \
    int c_ = kbase + (sidx)*16 + tig*2;                                         \
    cpa8(sb0 + d_*4096,        Alo + c_);                                       \
    cpa8(sb0 + d_*4096 + 1024, Ahi + c_);                                       \
    cpa8(sb0 + d_*4096 + 2048, Alo + c_ + 8);                                   \
    cpa8(sb0 + d_*4096 + 3072, Ahi + c_ + 8);                                   \
  }                                                                             \
  CP_COMMIT(); }

__global__ void __launch_bounds__(128, 4) k_main(const float* __restrict__ pm){
  const int kslice = blockIdx.x;     // 0..63
  const int mtile  = blockIdx.y;     // 0..9
  const int tid  = threadIdx.x;
  const int warp = tid >> 5;
  const int lane = tid & 31;
  const int tig  = lane & 3;
  const int g    = lane >> 2;
  const int row_lo = mtile*64 + warp*16 + g;
  const int row_hi = row_lo + 8;
  const bool vlo = row_lo < NROWS;
  const bool vhi = row_hi < NROWS;
  const float* Alo = pm + (size_t)(vlo ? row_lo : NROWS-1) * HW;
  const float* Ahi = pm + (size_t)(vhi ? row_hi : NROWS-1) * HW;
  const int kbase = kslice*KSPAN;

  __shared__ float2 As[DEPTH][4][128];   // 16KB: [buffer][slot][thread]
  const unsigned sb0 = (unsigned)__cvta_generic_to_shared(&As[0][0][tid]);

  float aP[32], aD[32];
#pragma unroll
  for (int i=0;i<32;i++){ aP[i]=0.f; aD[i]=0.f; }
  float ns_lo=0.f, ns_hi=0.f;
  float xmx_lo=-3e38f, ymx_lo=-3e38f, xmn_lo=3e38f, ymn_lo=3e38f;
  float xmx_hi=-3e38f, ymx_hi=-3e38f, xmn_hi=3e38f, ymn_hi=3e38f;
  float fxb = 0.f;                       // kbase % 256 == 0
  float fy  = (float)(kbase >> 8);
  const float ltig2 = (float)(tig*2);

  const unsigned* bbase = g_bfrag + (size_t)((kslice*KSTEPS)*32 + lane)*16;

  LOADA(0); LOADA(1); LOADA(2);

#pragma unroll 1
  for (int s = 0; s < KSTEPS; s++){
    LOADA(s+3);
    CP_WAIT3();
    int d = s & (DEPTH-1);
    float2 v0 = As[d][0][tid];
    float2 v1 = As[d][1][tid];
    float2 v2 = As[d][2][tid];
    float2 v3 = As[d][3][tid];
    if (!vlo){ v0.x=0.f; v0.y=0.f; v2.x=0.f; v2.y=0.f; }
    if (!vhi){ v1.x=0.f; v1.y=0.f; v3.x=0.f; v3.y=0.f; }

    const uint4* bp = (const uint4*)(bbase + (size_t)s*512);
    uint4 q0 = bp[0], q1 = bp[1], q2 = bp[2], q3 = bp[3];

    unsigned ap0,ad0,ap1,ad1,ap2,ad2,ap3,ad3;
    float xcl = fxb + ltig2;
    TF2(v0, xcl,     fy, ap0, ad0, ns_lo, xmx_lo, xmn_lo, ymx_lo, ymn_lo);
    TF2(v1, xcl,     fy, ap1, ad1, ns_hi, xmx_hi, xmn_hi, ymx_hi, ymn_hi);
    TF2(v2, xcl+8.f, fy, ap2, ad2, ns_lo, xmx_lo, xmn_lo, ymx_lo, ymn_lo);
    TF2(v3, xcl+8.f, fy, ap3, ad3, ns_hi, xmx_hi, xmn_hi, ymx_hi, ymn_hi);

    mma16816(aP+0,  ap0,ap1,ap2,ap3, q0.x,q0.y);
    mma16816(aP+4,  ap0,ap1,ap2,ap3, q0.z,q0.w);
    mma16816(aP+8,  ap0,ap1,ap2,ap3, q1.x,q1.y);
    mma16816(aP+12, ap0,ap1,ap2,ap3, q1.z,q1.w);
    mma16816(aP+16, ap0,ap1,ap2,ap3, q2.x,q2.y);
    mma16816(aP+20, ap0,ap1,ap2,ap3, q2.z,q2.w);
    mma16816(aP+24, ap0,ap1,ap2,ap3, q3.x,q3.y);
    mma16816(aP+28, ap0,ap1,ap2,ap3, q3.z,q3.w);
    mma16816(aD+0,  ad0,ad1,ad2,ad3, q0.x,q0.y);
    mma16816(aD+4,  ad0,ad1,ad2,ad3, q0.z,q0.w);
    mma16816(aD+8,  ad0,ad1,ad2,ad3, q1.x,q1.y);
    mma16816(aD+12, ad0,ad1,ad2,ad3, q1.z,q1.w);
    mma16816(aD+16, ad0,ad1,ad2,ad3, q2.x,q2.y);
    mma16816(aD+20, ad0,ad1,ad2,ad3, q2.z,q2.w);
    mma16816(aD+24, ad0,ad1,ad2,ad3, q3.x,q3.y);
    mma16816(aD+28, ad0,ad1,ad2,ad3, q3.z,q3.w);

    fxb += 16.f;
    if (fxb > 255.f){ fxb = 0.f; fy += 1.f; }
  }

  // write per-slice partials (unique writer per element -> deterministic)
  float* PP = g_partP + (size_t)kslice*NPAD*NT;
  float* PD = g_partD + (size_t)kslice*NPAD*NT;
#pragma unroll
  for (int t=0;t<8;t++){
    int cb = t*8 + tig*2;
    PP[row_lo*NT + cb]   = aP[t*4+0];
    PP[row_lo*NT + cb+1] = aP[t*4+1];
    PP[row_hi*NT + cb]   = aP[t*4+2];
    PP[row_hi*NT + cb+1] = aP[t*4+3];
    PD[row_lo*NT + cb]   = aD[t*4+0];
    PD[row_lo*NT + cb+1] = aD[t*4+1];
    PD[row_hi*NT + cb]   = aD[t*4+2];
    PD[row_hi*NT + cb+1] = aD[t*4+3];
  }

  QSUM(ns_lo); QSUM(ns_hi);
  QMAX(xmx_lo); QMAX(ymx_lo); QMIN(xmn_lo); QMIN(ymn_lo);
  QMAX(xmx_hi); QMAX(ymx_hi); QMIN(xmn_hi); QMIN(ymn_hi);
  if (tig == 0){
    g_partNS[kslice*NPAD + row_lo] = ns_lo;
    g_partNS[kslice*NPAD + row_hi] = ns_hi;
    if (vlo){
      atomicMin(&g_pmm[row_lo*4+0], f2o(xmn_lo));
      atomicMin(&g_pmm[row_lo*4+1], f2o(ymn_lo));
      atomicMax(&g_pmm[row_lo*4+2], f2o(xmx_lo));
      atomicMax(&g_pmm[row_lo*4+3], f2o(ymx_lo));
    }
    if (vhi){
      atomicMin(&g_pmm[row_hi*4+0], f2o(xmn_hi));
      atomicMin(&g_pmm[row_hi*4+1], f2o(ymn_hi));
      atomicMax(&g_pmm[row_hi*4+2], f2o(xmx_hi));
      atomicMax(&g_pmm[row_hi*4+3], f2o(ymx_hi));
    }
  }
}

// ---------------- final: per-row slice reduction + cost assembly ----------------
__device__ __forceinline__ float giou_fn(float a0,float a1,float a2,float a3,
                                         float b0,float b1,float b2,float b3){
  float area1 = (a2-a0)*(a3-a1);
  float area2 = (b2-b0)*(b3-b1);
  float ltx = fmaxf(a0,b0), lty = fmaxf(a1,b1);
  float rbx = fminf(a2,b2), rby = fminf(a3,b3);
  float wx = fmaxf(rbx-ltx, 0.f), wy = fmaxf(rby-lty, 0.f);
  float inter = wx*wy;
  float uni = area1 + area2 - inter;
  float iou = inter / uni;
  float lex = fminf(a0,b0), ley = fminf(a1,b1);
  float rex = fmaxf(a2,b2), rey = fmaxf(a3,b3);
  float ewx = fmaxf(rex-lex, 0.f), ewy = fmaxf(rey-ley, 0.f);
  float ea = ewx*ewy;
  return iou - (ea - uni)/ea;
}

__global__ void k_final(const float* __restrict__ logits, const float* __restrict__ pboxes,
                        const float* __restrict__ tboxes, const int* __restrict__ tids,
                        float* __restrict__ out){
  const int i = blockIdx.x;
  const int j = threadIdx.x;
  __shared__ float sP[NT], sD[NT], sNS;

  {
    float sp = 0.f, sd = 0.f;
#pragma unroll 1
    for (int s=0;s<KSLICES;s++){
      sp += g_partP[(size_t)s*NPAD*NT + i*NT + j];
      sd += g_partD[(size_t)s*NPAD*NT + i*NT + j];
    }
    sP[j] = sp; sD[j] = sd;
  }
  if (j == 61){
    float ns = 0.f;
#pragma unroll 1
    for (int s=0;s<KSLICES;s++) ns += g_partNS[s*NPAD + i];
    sNS = ns;
  }
  __syncthreads();
  if (j >= TT) return;

  float tsum = 0.f, txn = 1e8f, tyn = 1e8f, txx = 0.f, tyx = 0.f;
#pragma unroll 1
  for (int c=0;c<TCHUNKS;c++){
    tsum += g_tc[c*NT + j];
    txn = fminf(txn, g_txn[c*NT + j]); tyn = fminf(tyn, g_tyn[c*NT + j]);
    txx = fmaxf(txx, g_txx[c*NT + j]); tyx = fmaxf(tyx, g_tyx[c*NT + j]);
  }

  float pcx = pboxes[i*4+0], pcy = pboxes[i*4+1], pw = pboxes[i*4+2], ph = pboxes[i*4+3];
  float p0 = pcx-0.5f*pw, p1 = pcy-0.5f*ph, p2 = pcx+0.5f*pw, p3 = pcy+0.5f*ph;

  float mx = o2f(g_pmm[i*4+0]), my = o2f(g_pmm[i*4+1]);
  float mw = o2f(g_pmm[i*4+2]), mh = o2f(g_pmm[i*4+3]);
  float q0 = mx-0.5f*mw, q1 = my-0.5f*mh, q2 = mx+0.5f*mw, q3 = my+0.5f*mh;

  float psum = sP[TT];
  float nsum = sNS;

  float tcx = tboxes[j*4+0], tcy = tboxes[j*4+1], tw = tboxes[j*4+2], th = tboxes[j*4+3];
  float t0 = tcx-0.5f*tw, t1 = tcy-0.5f*th, t2 = tcx+0.5f*tw, t3 = tcy+0.5f*th;

  float cost_bbox = fabsf(pcx-tcx)+fabsf(pcy-tcy)+fabsf(pw-tw)+fabsf(ph-th);
  float g1 = giou_fn(p0,p1,p2,p3, t0,t1,t2,t3);

  float u0 = txn-0.5f*txx, u1 = tyn-0.5f*tyx, u2 = txn+0.5f*txx, u3 = tyn+0.5f*tyx;
  float g2 = giou_fn(q0,q1,q2,q3, u0,u1,u2,u3);

  int id = tids[j];
  float lg = logits[i*CLS + id];
  float pp = 1.f/(1.f + expf(-lg));
  float posc = 0.25f*(1.f-pp)*(1.f-pp)*(-logf(pp + 1e-8f));
  float negc = 0.75f*pp*pp*(-logf(1.f-pp + 1e-8f));
  float cclass = posc - negc;

  float inter = sP[j];
  float dice  = 1.f - (2.f*inter + 1e-5f)/(psum + tsum + 1e-5f);
  float dd    = sD[j];
  float focal = (dd + nsum) * (1.0f/65536.0f);

  out[i*TT + j] = cost_bbox + cclass - g1 - g2 + dice + focal;
}

// ---------------- launch ----------------
extern "C" void kernel_launch(void* const* d_in, const int* in_sizes, int n_in,
                              void* d_out, int out_size){
  (void)in_sizes; (void)n_in; (void)out_size;
  const float* logits = (const float*)d_in[0];
  const float* pboxes = (const float*)d_in[1];
  const float* pmasks = (const float*)d_in[2];
  const float* tboxes = (const float*)d_in[3];
  const int*   tids   = (const int*)d_in[4];
  const int*   tmasks = (const int*)d_in[5];
  float* out = (float*)d_out;

  k_prep<<<PREP_GRID, 256>>>(tmasks);
  k_main<<<dim3(KSLICES, MTILES), 128>>>(pmasks);
  k_final<<<NROWS, NT>>>(logits, pboxes, tboxes, tids, out);
}